// round 7
// baseline (speedup 1.0000x reference)
#include <cuda_runtime.h>

// SSIM_79886391705722 — fused separable-Gaussian SSIM, f32x2, direct-gmem
// h-pass (no input staging), 6 blocks/SM. GB300 sm_103a.
// raw/dst: [32,3,512,512] f32. Crop 4 -> 11x11 gaussian (valid) -> SSIM
// (scale-folded C1=1e-4, C2=9e-4) -> per-batch mean [32].

typedef unsigned long long u64;

#define TILE_W  32
#define TILE_H  40
#define IN_H    50
#define P_H     33     // ulonglong2 pitch (odd) -> conflict-free
#define OUT_DIM 494

// Normalized 1D Gaussian (ws=11, sigma=1.5); symmetric
#define G0 0.00102838f
#define G1 0.00759875f
#define G2 0.03600078f
#define G3 0.10936070f
#define G4 0.21300554f
#define G5 0.26601173f

__device__ __forceinline__ u64 pack2(float lo, float hi) {
    u64 r; asm("mov.b64 %0, {%1,%2};" : "=l"(r) : "f"(lo), "f"(hi)); return r;
}
__device__ __forceinline__ void unpack2(u64 v, float& lo, float& hi) {
    asm("mov.b64 {%0,%1}, %2;" : "=f"(lo), "=f"(hi) : "l"(v));
}
__device__ __forceinline__ u64 mul2(u64 a, u64 b) {
    u64 r; asm("mul.rn.f32x2 %0, %1, %2;" : "=l"(r) : "l"(a), "l"(b)); return r;
}
__device__ __forceinline__ u64 fma2(u64 a, u64 b, u64 c) {
    u64 r; asm("fma.rn.f32x2 %0, %1, %2, %3;" : "=l"(r) : "l"(a), "l"(b), "l"(c)); return r;
}

__global__ __launch_bounds__(32) void ssim_zero(float* out) {
    out[threadIdx.x] = 0.0f;
}

__global__ __launch_bounds__(256, 6) void ssim_main(const float* __restrict__ raw,
                                                    const float* __restrict__ dst,
                                                    float* __restrict__ out) {
    __shared__ ulonglong2 s_h[IN_H * P_H];   // {m=(mr,md), q=(rr+dd,rd)} 26.4KB
    __shared__ float      s_red[8];

    const int tid = threadIdx.x;
    const int z   = blockIdx.z;                  // b*3 + c
    const size_t plane = (size_t)z * 512 * 512;
    const float* rp = raw + plane;
    const float* dp = dst + plane;

    const float gv[6] = {G0, G1, G2, G3, G4, G5};
    u64 g2v[6];
    #pragma unroll
    for (int i = 0; i < 6; i++) g2v[i] = pack2(gv[i], gv[i]);
    #define GW2(j) g2v[(j) < 6 ? (j) : 10 - (j)]

    const int row0 = blockIdx.y * TILE_H + 4;
    const int col0 = blockIdx.x * TILE_W + 4;    // even -> float2 aligned
    const bool edge = (blockIdx.x == 15) || (blockIdx.y == 12);

    // ---- Phase A: horizontal 11-tap straight from gmem; strips of 4 ----
    // Half-warp = 16 consecutive y at one strip (conflict-free STS).
    for (int task = tid; task < 512; task += 256) {
        int y = (task & 15) | ((task >> 7) << 4);
        if (y < IN_H) {
            int x0  = ((task >> 4) & 7) << 2;
            int gr  = row0 + y;
            int gc0 = col0 + x0;
            const float2* rrow = reinterpret_cast<const float2*>(rp + (size_t)gr * 512 + gc0);
            const float2* drow = reinterpret_cast<const float2*>(dp + (size_t)gr * 512 + gc0);
            float2 rv[7], dv[7];
            if (!edge) {
                #pragma unroll
                for (int i = 0; i < 7; i++) { rv[i] = __ldg(rrow + i); dv[i] = __ldg(drow + i); }
            } else {
                bool rok = (gr <= 511);
                #pragma unroll
                for (int i = 0; i < 7; i++) {
                    bool ok = rok && (gc0 + 2 * i <= 510);
                    rv[i] = ok ? __ldg(rrow + i) : make_float2(0.f, 0.f);
                    dv[i] = ok ? __ldg(drow + i) : make_float2(0.f, 0.f);
                }
            }
            u64 am[4] = {0, 0, 0, 0};
            u64 aq[4] = {0, 0, 0, 0};
            #pragma unroll
            for (int h = 0; h < 7; h++) {
                #pragma unroll
                for (int s = 0; s < 2; s++) {
                    int i    = 2 * h + s;
                    float r  = s ? rv[h].y : rv[h].x;
                    float d  = s ? dv[h].y : dv[h].x;
                    u64 v    = pack2(r, d);
                    u64 sq   = mul2(v, v);
                    float rr, dd;
                    unpack2(sq, rr, dd);
                    u64 q    = pack2(rr + dd, r * d);
                    #pragma unroll
                    for (int k = 0; k < 4; k++) {
                        int j = i - k;
                        if (j >= 0 && j < 11) {
                            am[k] = fma2(GW2(j), v, am[k]);
                            aq[k] = fma2(GW2(j), q, aq[k]);
                        }
                    }
                }
            }
            int hb = y * P_H + x0;
            #pragma unroll
            for (int k = 0; k < 4; k++) {
                ulonglong2 hp; hp.x = am[k]; hp.y = aq[k];
                s_h[hb + k] = hp;
            }
        }
    }
    __syncthreads();

    // ---- Phase B: vertical 11-tap, strips of 5 + SSIM + reduce ----
    float local = 0.0f;
    {
        int x  = tid & 31;
        int y0 = (tid >> 5) * 5;
        u64 am[5] = {0, 0, 0, 0, 0};
        u64 aq[5] = {0, 0, 0, 0, 0};
        const ulonglong2* bh = &s_h[y0 * P_H + x];
        #pragma unroll
        for (int j = 0; j < 15; j++) {
            ulonglong2 hp = bh[j * P_H];
            #pragma unroll
            for (int k = 0; k < 5; k++) {
                int t = j - k;
                if (t >= 0 && t < 11) {
                    am[k] = fma2(GW2(t), hp.x, am[k]);
                    aq[k] = fma2(GW2(t), hp.y, aq[k]);
                }
            }
        }
        const float C1 = 1.0e-4f;    // (0.01)^2  — 255 scale folded out
        const float C2 = 9.0e-4f;    // (0.03)^2
        int ox  = blockIdx.x * TILE_W + x;
        int oyb = blockIdx.y * TILE_H + y0;
        if (ox < OUT_DIM) {
            #pragma unroll
            for (int k = 0; k < 5; k++) {
                if ((oyb + k) < OUT_DIM) {
                    float a, b, srrdd, srd;
                    unpack2(am[k], a, b);
                    unpack2(aq[k], srrdd, srd);
                    float ab  = a * b;
                    float cov = srd - ab;
                    float var = srrdd - a * a - b * b;
                    float num = (2.0f * ab + C1) * (2.0f * cov + C2);
                    float den = (a * a + b * b + C1) * (var + C2);
                    local += __fdividef(num, den);
                }
            }
        }
    }

    #pragma unroll
    for (int o = 16; o > 0; o >>= 1)
        local += __shfl_down_sync(0xffffffff, local, o);
    if ((tid & 31) == 0) s_red[tid >> 5] = local;
    __syncthreads();
    if (tid < 8) {
        local = s_red[tid];
        #pragma unroll
        for (int o = 4; o > 0; o >>= 1)
            local += __shfl_down_sync(0xff, local, o);
        if (tid == 0)
            atomicAdd(&out[z / 3], local * (1.0f / 732108.0f)); // 1/(3*494^2)
    }
}

extern "C" void kernel_launch(void* const* d_in, const int* in_sizes, int n_in,
                              void* d_out, int out_size) {
    const float* raw = (const float*)d_in[0];
    const float* dst = (const float*)d_in[1];
    float* out = (float*)d_out;

    ssim_zero<<<1, 32>>>(out);
    dim3 grid(16, 13, 96);   // 32x40 tiles over 494x494, z = b*3+c
    ssim_main<<<grid, 256>>>(raw, dst, out);
}

// round 8
// speedup vs baseline: 2.8489x; 2.8489x over previous
#include <cuda_runtime.h>

// SSIM_79886391705722 — fused separable-Gaussian SSIM, f32x2, bf16x2 input
// staging, strip-8/strip-7, 32x54 tile, 5 blocks/SM. GB300 sm_103a.
// raw/dst: [32,3,512,512] f32. Crop 4 -> 11x11 gaussian (valid) -> SSIM
// (scale-folded C1=1e-4, C2=9e-4) -> per-batch mean [32].

typedef unsigned long long u64;
typedef unsigned int u32;

#define TILE_W  32
#define TILE_H  54
#define IN_H    64     // TILE_H + 10
#define P_RD    43     // u32 pitch (odd) -> conflict-free y-consecutive lanes
#define P_H     33     // ulonglong2 pitch (odd)
#define OUT_DIM 494

// Normalized 1D Gaussian (ws=11, sigma=1.5); symmetric
#define G0 0.00102838f
#define G1 0.00759875f
#define G2 0.03600078f
#define G3 0.10936070f
#define G4 0.21300554f
#define G5 0.26601173f

__device__ __forceinline__ u64 pack2(float lo, float hi) {
    u64 r; asm("mov.b64 %0, {%1,%2};" : "=l"(r) : "f"(lo), "f"(hi)); return r;
}
__device__ __forceinline__ void unpack2(u64 v, float& lo, float& hi) {
    asm("mov.b64 {%0,%1}, %2;" : "=f"(lo), "=f"(hi) : "l"(v));
}
__device__ __forceinline__ u64 fma2(u64 a, u64 b, u64 c) {
    u64 r; asm("fma.rn.f32x2 %0, %1, %2, %3;" : "=l"(r) : "l"(a), "l"(b), "l"(c)); return r;
}
// pack (r,d) as bf16x2: hi=d, lo=r
__device__ __forceinline__ u32 bfpair(float r, float d) {
    u32 p; asm("cvt.rn.bf16x2.f32 %0, %1, %2;" : "=r"(p) : "f"(d), "f"(r)); return p;
}

__global__ __launch_bounds__(32) void ssim_zero(float* out) {
    out[threadIdx.x] = 0.0f;
}

__global__ __launch_bounds__(256, 5) void ssim_main(const float* __restrict__ raw,
                                                    const float* __restrict__ dst,
                                                    float* __restrict__ out) {
    __shared__ u32        s_rd[IN_H * P_RD];   // (r,d) bf16x2        11.0KB
    __shared__ ulonglong2 s_h[IN_H * P_H];     // {m=(mr,md), q=(rr+dd,rd)} 33.8KB
    __shared__ float      s_red[8];

    const int tid = threadIdx.x;
    const int z   = blockIdx.z;                  // b*3 + c
    const size_t plane = (size_t)z * 512 * 512;
    const float* rp = raw + plane;
    const float* dp = dst + plane;

    const float gv[6] = {G0, G1, G2, G3, G4, G5};
    u64 g2v[6];
    #pragma unroll
    for (int i = 0; i < 6; i++) g2v[i] = pack2(gv[i], gv[i]);
    #define GW2(j) g2v[(j) < 6 ? (j) : 10 - (j)]

    const int row0 = blockIdx.y * TILE_H + 4;
    const int col0 = blockIdx.x * TILE_W + 4;    // even -> float2 aligned

    // ---- Phase 1: load 64x42 halo of (r,d) as bf16x2 pairs ----
    for (int i = tid; i < IN_H * 21; i += 256) {
        int y  = i / 21;
        int xp = i - y * 21;
        int x  = xp * 2;
        int gr = row0 + y, gc = col0 + x;
        float r0 = 0.f, r1 = 0.f, d0 = 0.f, d1 = 0.f;
        if (gr <= 511 && gc <= 511) {            // gc even -> gc+1 <= 511 ok
            size_t off = (size_t)gr * 512 + gc;
            float2 rv = __ldg(reinterpret_cast<const float2*>(rp + off));
            float2 dv = __ldg(reinterpret_cast<const float2*>(dp + off));
            r0 = rv.x; d0 = dv.x; r1 = rv.y; d1 = dv.y;
        }
        s_rd[y * P_RD + x]     = bfpair(r0, d0);
        s_rd[y * P_RD + x + 1] = bfpair(r1, d1);
    }
    __syncthreads();

    // ---- Phase 2: horizontal 11-tap, strips of 8; 64 rows x 4 strips = 256 ----
    // Warp = 32 consecutive y at one strip -> conflict-free LDS.32 / STS.128.
    {
        int y  = tid & 63;
        int x0 = (tid >> 6) << 3;
        const u32* base = &s_rd[y * P_RD + x0];
        u64 am[8], aq[8];
        #pragma unroll
        for (int k = 0; k < 8; k++) { am[k] = 0; aq[k] = 0; }
        #pragma unroll
        for (int i = 0; i < 18; i++) {
            u32 v   = base[i];
            float r = __uint_as_float(v << 16);           // exact bf16->f32
            float d = __uint_as_float(v & 0xffff0000u);
            u64 m = pack2(r, d);
            u64 q = pack2(fmaf(r, r, d * d), r * d);
            #pragma unroll
            for (int k = 0; k < 8; k++) {
                int j = i - k;
                if (j >= 0 && j < 11) {
                    am[k] = fma2(GW2(j), m, am[k]);
                    aq[k] = fma2(GW2(j), q, aq[k]);
                }
            }
        }
        int hb = y * P_H + x0;
        #pragma unroll
        for (int k = 0; k < 8; k++) {
            ulonglong2 hp; hp.x = am[k]; hp.y = aq[k];
            s_h[hb + k] = hp;
        }
    }
    __syncthreads();

    // ---- Phase 3: vertical 11-tap, strips of 7 + SSIM + reduce (256 tasks) ----
    float local = 0.0f;
    {
        int x  = tid & 31;
        int y0 = (tid >> 5) * 7;
        u64 am[7], aq[7];
        #pragma unroll
        for (int k = 0; k < 7; k++) { am[k] = 0; aq[k] = 0; }
        #pragma unroll
        for (int j = 0; j < 17; j++) {
            int yy = y0 + j;
            if (yy > IN_H - 1) yy = IN_H - 1;   // overhang feeds discarded only
            ulonglong2 hp = s_h[yy * P_H + x];
            #pragma unroll
            for (int k = 0; k < 7; k++) {
                int t = j - k;
                if (t >= 0 && t < 11) {
                    am[k] = fma2(GW2(t), hp.x, am[k]);
                    aq[k] = fma2(GW2(t), hp.y, aq[k]);
                }
            }
        }
        const float C1 = 1.0e-4f;    // (0.01)^2  — 255 scale folded out
        const float C2 = 9.0e-4f;    // (0.03)^2
        int ox  = blockIdx.x * TILE_W + x;
        int oyb = blockIdx.y * TILE_H + y0;
        if (ox < OUT_DIM) {
            #pragma unroll
            for (int k = 0; k < 7; k++) {
                if ((y0 + k) < TILE_H && (oyb + k) < OUT_DIM) {
                    float a, b, srrdd, srd;
                    unpack2(am[k], a, b);
                    unpack2(aq[k], srrdd, srd);
                    float ab  = a * b;
                    float cov = srd - ab;
                    float var = srrdd - a * a - b * b;
                    float num = (2.0f * ab + C1) * (2.0f * cov + C2);
                    float den = (a * a + b * b + C1) * (var + C2);
                    local += __fdividef(num, den);
                }
            }
        }
    }

    #pragma unroll
    for (int o = 16; o > 0; o >>= 1)
        local += __shfl_down_sync(0xffffffff, local, o);
    if ((tid & 31) == 0) s_red[tid >> 5] = local;
    __syncthreads();
    if (tid < 8) {
        local = s_red[tid];
        #pragma unroll
        for (int o = 4; o > 0; o >>= 1)
            local += __shfl_down_sync(0xff, local, o);
        if (tid == 0)
            atomicAdd(&out[z / 3], local * (1.0f / 732108.0f)); // 1/(3*494^2)
    }
}

extern "C" void kernel_launch(void* const* d_in, const int* in_sizes, int n_in,
                              void* d_out, int out_size) {
    const float* raw = (const float*)d_in[0];
    const float* dst = (const float*)d_in[1];
    float* out = (float*)d_out;

    ssim_zero<<<1, 32>>>(out);
    dim3 grid(16, 10, 96);   // 32x54 tiles over 494x494, z = b*3+c
    ssim_main<<<grid, 256>>>(raw, dst, out);
}

// round 9
// speedup vs baseline: 3.4180x; 1.1998x over previous
#include <cuda_runtime.h>
#include <cuda_fp16.h>

// SSIM_79886391705722 — fused separable-Gaussian SSIM, f32x2, f16x2 input
// staging (precision-safe), float4 gmem loads, strip-8/strip-7, 32x54 tile,
// 5 blocks/SM. GB300 sm_103a.
// raw/dst: [32,3,512,512] f32. Crop 4 -> 11x11 gaussian (valid) -> SSIM
// (scale-folded C1=1e-4, C2=9e-4) -> per-batch mean [32].

typedef unsigned long long u64;
typedef unsigned int u32;

#define TILE_W  32
#define TILE_H  54
#define IN_H    64     // TILE_H + 10
#define P_RD    43     // u32 pitch (odd) -> conflict-free y-consecutive lanes
#define P_H     33     // ulonglong2 pitch (odd)
#define OUT_DIM 494

// Normalized 1D Gaussian (ws=11, sigma=1.5); symmetric
#define G0 0.00102838f
#define G1 0.00759875f
#define G2 0.03600078f
#define G3 0.10936070f
#define G4 0.21300554f
#define G5 0.26601173f

__device__ __forceinline__ u64 pack2(float lo, float hi) {
    u64 r; asm("mov.b64 %0, {%1,%2};" : "=l"(r) : "f"(lo), "f"(hi)); return r;
}
__device__ __forceinline__ void unpack2(u64 v, float& lo, float& hi) {
    asm("mov.b64 {%0,%1}, %2;" : "=f"(lo), "=f"(hi) : "l"(v));
}
__device__ __forceinline__ u64 fma2(u64 a, u64 b, u64 c) {
    u64 r; asm("fma.rn.f32x2 %0, %1, %2, %3;" : "=l"(r) : "l"(a), "l"(b), "l"(c)); return r;
}
// pack (r,d) as f16x2: lo=r, hi=d
__device__ __forceinline__ u32 hpair(float r, float d) {
    u32 p; asm("cvt.rn.f16x2.f32 %0, %1, %2;" : "=r"(p) : "f"(d), "f"(r)); return p;
}

__global__ __launch_bounds__(32) void ssim_zero(float* out) {
    out[threadIdx.x] = 0.0f;
}

__global__ __launch_bounds__(256, 5) void ssim_main(const float* __restrict__ raw,
                                                    const float* __restrict__ dst,
                                                    float* __restrict__ out) {
    __shared__ u32        s_rd[IN_H * P_RD];   // (r,d) f16x2         11.0KB
    __shared__ ulonglong2 s_h[IN_H * P_H];     // {m=(mr,md), q=(rr+dd,rd)} 33.8KB
    __shared__ float      s_red[8];

    const int tid = threadIdx.x;
    const int z   = blockIdx.z;                  // b*3 + c
    const size_t plane = (size_t)z * 512 * 512;
    const float* rp = raw + plane;
    const float* dp = dst + plane;

    const float gv[6] = {G0, G1, G2, G3, G4, G5};
    u64 g2v[6];
    #pragma unroll
    for (int i = 0; i < 6; i++) g2v[i] = pack2(gv[i], gv[i]);
    #define GW2(j) g2v[(j) < 6 ? (j) : 10 - (j)]

    const int row0 = blockIdx.y * TILE_H + 4;
    const int col0 = blockIdx.x * TILE_W + 4;    // ≡ 4 mod 32 -> float4 aligned

    // ---- Phase 1: load 64x42 halo of (r,d) as f16x2, float4 gmem loads ----
    // 11 groups of 4 pixels per row; group 10 stores only 2 (pitch 43).
    for (int i = tid; i < IN_H * 11; i += 256) {
        int y = i / 11;
        int g = i - y * 11;
        int x = g << 2;
        int gr = row0 + y, gc = col0 + x;
        float4 r4 = make_float4(0.f, 0.f, 0.f, 0.f);
        float4 d4 = r4;
        if (gr <= 511 && gc <= 508) {            // gc % 4 == 0: no partial case
            size_t off = (size_t)gr * 512 + gc;
            r4 = __ldg(reinterpret_cast<const float4*>(rp + off));
            d4 = __ldg(reinterpret_cast<const float4*>(dp + off));
        }
        int sb = y * P_RD + x;
        s_rd[sb]     = hpair(r4.x, d4.x);
        s_rd[sb + 1] = hpair(r4.y, d4.y);
        if (g < 10) {
            s_rd[sb + 2] = hpair(r4.z, d4.z);
            s_rd[sb + 3] = hpair(r4.w, d4.w);
        }
    }
    __syncthreads();

    // ---- Phase 2: horizontal 11-tap, strips of 8; 64 rows x 4 strips = 256 ----
    // Warp = 32 consecutive y at one strip -> conflict-free LDS.32 / STS.128.
    {
        int y  = tid & 63;
        int x0 = (tid >> 6) << 3;
        const u32* base = &s_rd[y * P_RD + x0];
        u64 am[8], aq[8];
        #pragma unroll
        for (int k = 0; k < 8; k++) { am[k] = 0; aq[k] = 0; }
        #pragma unroll
        for (int i = 0; i < 18; i++) {
            u32 v = base[i];
            float2 f = __half22float2(*reinterpret_cast<const __half2*>(&v));
            float r = f.x, d = f.y;
            u64 m = pack2(r, d);
            u64 q = pack2(fmaf(r, r, d * d), r * d);
            #pragma unroll
            for (int k = 0; k < 8; k++) {
                int j = i - k;
                if (j >= 0 && j < 11) {
                    am[k] = fma2(GW2(j), m, am[k]);
                    aq[k] = fma2(GW2(j), q, aq[k]);
                }
            }
        }
        int hb = y * P_H + x0;
        #pragma unroll
        for (int k = 0; k < 8; k++) {
            ulonglong2 hp; hp.x = am[k]; hp.y = aq[k];
            s_h[hb + k] = hp;
        }
    }
    __syncthreads();

    // ---- Phase 3: vertical 11-tap, strips of 7 + SSIM + reduce (256 tasks) ----
    float local = 0.0f;
    {
        int x  = tid & 31;
        int y0 = (tid >> 5) * 7;
        u64 am[7], aq[7];
        #pragma unroll
        for (int k = 0; k < 7; k++) { am[k] = 0; aq[k] = 0; }
        #pragma unroll
        for (int j = 0; j < 17; j++) {
            int yy = y0 + j;
            if (yy > IN_H - 1) yy = IN_H - 1;   // overhang feeds discarded only
            ulonglong2 hp = s_h[yy * P_H + x];
            #pragma unroll
            for (int k = 0; k < 7; k++) {
                int t = j - k;
                if (t >= 0 && t < 11) {
                    am[k] = fma2(GW2(t), hp.x, am[k]);
                    aq[k] = fma2(GW2(t), hp.y, aq[k]);
                }
            }
        }
        const float C1 = 1.0e-4f;    // (0.01)^2  — 255 scale folded out
        const float C2 = 9.0e-4f;    // (0.03)^2
        int ox  = blockIdx.x * TILE_W + x;
        int oyb = blockIdx.y * TILE_H + y0;
        if (ox < OUT_DIM) {
            #pragma unroll
            for (int k = 0; k < 7; k++) {
                if ((y0 + k) < TILE_H && (oyb + k) < OUT_DIM) {
                    float a, b, srrdd, srd;
                    unpack2(am[k], a, b);
                    unpack2(aq[k], srrdd, srd);
                    float ab  = a * b;
                    float cov = srd - ab;
                    float var = srrdd - a * a - b * b;
                    float num = (2.0f * ab + C1) * (2.0f * cov + C2);
                    float den = (a * a + b * b + C1) * (var + C2);
                    local += __fdividef(num, den);
                }
            }
        }
    }

    #pragma unroll
    for (int o = 16; o > 0; o >>= 1)
        local += __shfl_down_sync(0xffffffff, local, o);
    if ((tid & 31) == 0) s_red[tid >> 5] = local;
    __syncthreads();
    if (tid < 8) {
        local = s_red[tid];
        #pragma unroll
        for (int o = 4; o > 0; o >>= 1)
            local += __shfl_down_sync(0xff, local, o);
        if (tid == 0)
            atomicAdd(&out[z / 3], local * (1.0f / 732108.0f)); // 1/(3*494^2)
    }
}

extern "C" void kernel_launch(void* const* d_in, const int* in_sizes, int n_in,
                              void* d_out, int out_size) {
    const float* raw = (const float*)d_in[0];
    const float* dst = (const float*)d_in[1];
    float* out = (float*)d_out;

    ssim_zero<<<1, 32>>>(out);
    dim3 grid(16, 10, 96);   // 32x54 tiles over 494x494, z = b*3+c
    ssim_main<<<grid, 256>>>(raw, dst, out);
}

// round 10
// speedup vs baseline: 3.4246x; 1.0019x over previous
#include <cuda_runtime.h>
#include <cuda_fp16.h>

// SSIM_79886391705722 — fused separable-Gaussian SSIM, f32x2, f16x2 staging,
// 320-thread blocks, 32x70 tile, exact-fit phases, 4 blocks/SM, dyn smem.
// GB300 sm_103a.
// raw/dst: [32,3,512,512] f32. Crop 4 -> 11x11 gaussian (valid) -> SSIM
// (scale-folded C1=1e-4, C2=9e-4) -> per-batch mean [32].

typedef unsigned long long u64;
typedef unsigned int u32;

#define NTHR    320
#define TILE_W  32
#define TILE_H  70
#define IN_H    80     // TILE_H + 10
#define P_RD    43     // u32 pitch (odd)
#define P_H     33     // ulonglong2 pitch (odd)
#define OUT_DIM 494

#define SZ_RD   (IN_H * P_RD * 4)          // 13760
#define SZ_H    (IN_H * P_H * 16)          // 42240
#define SMEM_BYTES (SZ_RD + SZ_H + 64)     // + reduction pad

// Normalized 1D Gaussian (ws=11, sigma=1.5); symmetric
#define G0 0.00102838f
#define G1 0.00759875f
#define G2 0.03600078f
#define G3 0.10936070f
#define G4 0.21300554f
#define G5 0.26601173f

__device__ __forceinline__ u64 pack2(float lo, float hi) {
    u64 r; asm("mov.b64 %0, {%1,%2};" : "=l"(r) : "f"(lo), "f"(hi)); return r;
}
__device__ __forceinline__ void unpack2(u64 v, float& lo, float& hi) {
    asm("mov.b64 {%0,%1}, %2;" : "=f"(lo), "=f"(hi) : "l"(v));
}
__device__ __forceinline__ u64 fma2(u64 a, u64 b, u64 c) {
    u64 r; asm("fma.rn.f32x2 %0, %1, %2, %3;" : "=l"(r) : "l"(a), "l"(b), "l"(c)); return r;
}
// pack (r,d) as f16x2: lo=r, hi=d
__device__ __forceinline__ u32 hpair(float r, float d) {
    u32 p; asm("cvt.rn.f16x2.f32 %0, %1, %2;" : "=r"(p) : "f"(d), "f"(r)); return p;
}

__global__ __launch_bounds__(32) void ssim_zero(float* out) {
    out[threadIdx.x] = 0.0f;
}

__global__ __launch_bounds__(NTHR, 4) void ssim_main(const float* __restrict__ raw,
                                                     const float* __restrict__ dst,
                                                     float* __restrict__ out) {
    extern __shared__ char smem_raw[];
    u32*        s_rd  = reinterpret_cast<u32*>(smem_raw);            // f16x2 (r,d)
    ulonglong2* s_h   = reinterpret_cast<ulonglong2*>(smem_raw + SZ_RD);
    float*      s_red = reinterpret_cast<float*>(smem_raw + SZ_RD + SZ_H);

    const int tid = threadIdx.x;
    const int z   = blockIdx.z;                  // b*3 + c
    const size_t plane = (size_t)z * 512 * 512;
    const float* rp = raw + plane;
    const float* dp = dst + plane;

    const float gv[6] = {G0, G1, G2, G3, G4, G5};
    u64 g2v[6];
    #pragma unroll
    for (int i = 0; i < 6; i++) g2v[i] = pack2(gv[i], gv[i]);
    #define GW2(j) g2v[(j) < 6 ? (j) : 10 - (j)]

    const int row0 = blockIdx.y * TILE_H + 4;
    const int col0 = blockIdx.x * TILE_W + 4;    // ≡ 4 mod 32 -> float4 aligned

    // ---- Phase 1: load 80x42 halo of (r,d) as f16x2, float4 gmem loads ----
    // 11 groups of 4 pixels per row; group 10 stores only 2 (42-wide halo).
    for (int i = tid; i < IN_H * 11; i += NTHR) {
        int y = i / 11;
        int g = i - y * 11;
        int x = g << 2;
        int gr = row0 + y, gc = col0 + x;
        float4 r4 = make_float4(0.f, 0.f, 0.f, 0.f);
        float4 d4 = r4;
        if (gr <= 511 && gc <= 508) {            // gc % 4 == 0: no partial case
            size_t off = (size_t)gr * 512 + gc;
            r4 = __ldg(reinterpret_cast<const float4*>(rp + off));
            d4 = __ldg(reinterpret_cast<const float4*>(dp + off));
        }
        int sb = y * P_RD + x;
        s_rd[sb]     = hpair(r4.x, d4.x);
        s_rd[sb + 1] = hpair(r4.y, d4.y);
        if (g < 10) {
            s_rd[sb + 2] = hpair(r4.z, d4.z);
            s_rd[sb + 3] = hpair(r4.w, d4.w);
        }
    }
    __syncthreads();

    // ---- Phase 2: horizontal 11-tap, strip-8; 80 rows x 4 strips = 320 ----
    {
        int y  = tid % 80;
        int x0 = (tid / 80) << 3;
        const u32* base = &s_rd[y * P_RD + x0];
        u64 am[8], aq[8];
        #pragma unroll
        for (int k = 0; k < 8; k++) { am[k] = 0; aq[k] = 0; }
        #pragma unroll
        for (int i = 0; i < 18; i++) {
            u32 v = base[i];
            float2 f = __half22float2(*reinterpret_cast<const __half2*>(&v));
            float r = f.x, d = f.y;
            u64 m = pack2(r, d);
            u64 q = pack2(fmaf(r, r, d * d), r * d);
            #pragma unroll
            for (int k = 0; k < 8; k++) {
                int j = i - k;
                if (j >= 0 && j < 11) {
                    am[k] = fma2(GW2(j), m, am[k]);
                    aq[k] = fma2(GW2(j), q, aq[k]);
                }
            }
        }
        int hb = y * P_H + x0;
        #pragma unroll
        for (int k = 0; k < 8; k++) {
            ulonglong2 hp; hp.x = am[k]; hp.y = aq[k];
            s_h[hb + k] = hp;
        }
    }
    __syncthreads();

    // ---- Phase 3: vertical 11-tap, strip-7; 10 warps x 7 = 70 rows exact ----
    float local = 0.0f;
    {
        int x  = tid & 31;
        int y0 = (tid >> 5) * 7;                 // 0..63; max read y = 79
        u64 am[7], aq[7];
        #pragma unroll
        for (int k = 0; k < 7; k++) { am[k] = 0; aq[k] = 0; }
        const ulonglong2* bh = &s_h[y0 * P_H + x];
        #pragma unroll
        for (int j = 0; j < 17; j++) {
            ulonglong2 hp = bh[j * P_H];
            #pragma unroll
            for (int k = 0; k < 7; k++) {
                int t = j - k;
                if (t >= 0 && t < 11) {
                    am[k] = fma2(GW2(t), hp.x, am[k]);
                    aq[k] = fma2(GW2(t), hp.y, aq[k]);
                }
            }
        }
        const float C1 = 1.0e-4f;    // (0.01)^2  — 255 scale folded out
        const float C2 = 9.0e-4f;    // (0.03)^2
        int ox  = blockIdx.x * TILE_W + x;
        int oyb = blockIdx.y * TILE_H + y0;
        if (ox < OUT_DIM) {
            #pragma unroll
            for (int k = 0; k < 7; k++) {
                if ((oyb + k) < OUT_DIM) {
                    float a, b, srrdd, srd;
                    unpack2(am[k], a, b);
                    unpack2(aq[k], srrdd, srd);
                    float ab  = a * b;
                    float cov = srd - ab;
                    float var = srrdd - a * a - b * b;
                    float num = (2.0f * ab + C1) * (2.0f * cov + C2);
                    float den = (a * a + b * b + C1) * (var + C2);
                    local += __fdividef(num, den);
                }
            }
        }
    }

    #pragma unroll
    for (int o = 16; o > 0; o >>= 1)
        local += __shfl_down_sync(0xffffffff, local, o);
    if ((tid & 31) == 0) s_red[tid >> 5] = local;
    __syncthreads();
    if (tid < 16) {
        local = (tid < 10) ? s_red[tid] : 0.0f;
        #pragma unroll
        for (int o = 8; o > 0; o >>= 1)
            local += __shfl_down_sync(0xffff, local, o);
        if (tid == 0)
            atomicAdd(&out[z / 3], local * (1.0f / 732108.0f)); // 1/(3*494^2)
    }
}

extern "C" void kernel_launch(void* const* d_in, const int* in_sizes, int n_in,
                              void* d_out, int out_size) {
    const float* raw = (const float*)d_in[0];
    const float* dst = (const float*)d_in[1];
    float* out = (float*)d_out;

    cudaFuncSetAttribute(ssim_main, cudaFuncAttributeMaxDynamicSharedMemorySize,
                         SMEM_BYTES);

    ssim_zero<<<1, 32>>>(out);
    dim3 grid(16, 8, 96);    // 32x70 tiles over 494x494, z = b*3+c
    ssim_main<<<grid, NTHR, SMEM_BYTES>>>(raw, dst, out);
}

// round 11
// speedup vs baseline: 3.4515x; 1.0078x over previous
#include <cuda_runtime.h>
#include <cuda_fp16.h>

// SSIM_79886391705722 — fused separable-Gaussian SSIM, f32x2, f16x2 staging,
// 288 threads / 5 blocks-SM, 32x54 tile, early-exit on discarded rows/strips.
// GB300 sm_103a.
// raw/dst: [32,3,512,512] f32. Crop 4 -> 11x11 gaussian (valid) -> SSIM
// (scale-folded C1=1e-4, C2=9e-4) -> per-batch mean [32].

typedef unsigned long long u64;
typedef unsigned int u32;

#define NTHR    288
#define TILE_W  32
#define TILE_H  54
#define IN_H    64     // TILE_H + 10
#define P_RD    43     // u32 pitch (odd)
#define P_H     33     // ulonglong2 pitch (odd)
#define OUT_DIM 494

#define SZ_RD   (IN_H * P_RD * 4)          // 11008
#define SZ_H    (IN_H * P_H * 16)          // 33792
#define SMEM_BYTES (SZ_RD + SZ_H + 64)     // 44864

// Normalized 1D Gaussian (ws=11, sigma=1.5); symmetric
#define G0 0.00102838f
#define G1 0.00759875f
#define G2 0.03600078f
#define G3 0.10936070f
#define G4 0.21300554f
#define G5 0.26601173f

__device__ __forceinline__ u64 pack2(float lo, float hi) {
    u64 r; asm("mov.b64 %0, {%1,%2};" : "=l"(r) : "f"(lo), "f"(hi)); return r;
}
__device__ __forceinline__ void unpack2(u64 v, float& lo, float& hi) {
    asm("mov.b64 {%0,%1}, %2;" : "=f"(lo), "=f"(hi) : "l"(v));
}
__device__ __forceinline__ u64 fma2(u64 a, u64 b, u64 c) {
    u64 r; asm("fma.rn.f32x2 %0, %1, %2, %3;" : "=l"(r) : "l"(a), "l"(b), "l"(c)); return r;
}
// pack (r,d) as f16x2: lo=r, hi=d
__device__ __forceinline__ u32 hpair(float r, float d) {
    u32 p; asm("cvt.rn.f16x2.f32 %0, %1, %2;" : "=r"(p) : "f"(d), "f"(r)); return p;
}

__global__ __launch_bounds__(32) void ssim_zero(float* out) {
    out[threadIdx.x] = 0.0f;
}

__global__ __launch_bounds__(NTHR, 5) void ssim_main(const float* __restrict__ raw,
                                                     const float* __restrict__ dst,
                                                     float* __restrict__ out) {
    extern __shared__ char smem_raw[];
    u32*        s_rd  = reinterpret_cast<u32*>(smem_raw);            // f16x2 (r,d)
    ulonglong2* s_h   = reinterpret_cast<ulonglong2*>(smem_raw + SZ_RD);
    float*      s_red = reinterpret_cast<float*>(smem_raw + SZ_RD + SZ_H);

    const int tid = threadIdx.x;
    const int z   = blockIdx.z;                  // b*3 + c
    const size_t plane = (size_t)z * 512 * 512;
    const float* rp = raw + plane;
    const float* dp = dst + plane;

    const float gv[6] = {G0, G1, G2, G3, G4, G5};
    u64 g2v[6];
    #pragma unroll
    for (int i = 0; i < 6; i++) g2v[i] = pack2(gv[i], gv[i]);
    #define GW2(j) g2v[(j) < 6 ? (j) : 10 - (j)]

    const int oyb0 = blockIdx.y * TILE_H;        // first output row of tile
    const int row0 = oyb0 + 4;
    const int col0 = blockIdx.x * TILE_W + 4;    // ≡ 4 mod 32 -> float4 aligned

    // Rows of the h-plane actually needed by valid outputs (uniform per block).
    int ylim = OUT_DIM - oyb0 + 10;
    if (ylim > IN_H) ylim = IN_H;
    // h-cols needed by valid outputs (last x tile: outputs x<=13 -> cols<24).
    const int xlim = (blockIdx.x == 15) ? 24 : 42;

    // ---- Phase 1: load ylim x 42 halo of (r,d) as f16x2, float4 loads ----
    for (int i = tid; i < ylim * 11; i += NTHR) {
        int y = i / 11;
        int g = i - y * 11;
        int x = g << 2;
        int gr = row0 + y, gc = col0 + x;
        float4 r4 = make_float4(0.f, 0.f, 0.f, 0.f);
        float4 d4 = r4;
        if (gr <= 511 && gc <= 508) {            // gc % 4 == 0: no partial case
            size_t off = (size_t)gr * 512 + gc;
            r4 = __ldg(reinterpret_cast<const float4*>(rp + off));
            d4 = __ldg(reinterpret_cast<const float4*>(dp + off));
        }
        int sb = y * P_RD + x;
        s_rd[sb]     = hpair(r4.x, d4.x);
        s_rd[sb + 1] = hpair(r4.y, d4.y);
        if (g < 10) {
            s_rd[sb + 2] = hpair(r4.z, d4.z);
            s_rd[sb + 3] = hpair(r4.w, d4.w);
        }
    }
    __syncthreads();

    // ---- Phase 2: horizontal 11-tap, strip-4; 64 rows x 8 strips = 512 ----
    // Warp sees consecutive y at one strip -> conflict-free LDS.32 / STS.128.
    for (int task = tid; task < 512; task += NTHR) {
        int y  = task & 63;
        int x0 = (task >> 6) << 2;
        if (y < ylim && x0 < xlim) {
            const u32* base = &s_rd[y * P_RD + x0];
            u64 am[4] = {0, 0, 0, 0};
            u64 aq[4] = {0, 0, 0, 0};
            #pragma unroll
            for (int i = 0; i < 14; i++) {
                u32 v = base[i];
                float2 f = __half22float2(*reinterpret_cast<const __half2*>(&v));
                float r = f.x, d = f.y;
                u64 m = pack2(r, d);
                u64 q = pack2(fmaf(r, r, d * d), r * d);
                #pragma unroll
                for (int k = 0; k < 4; k++) {
                    int j = i - k;
                    if (j >= 0 && j < 11) {
                        am[k] = fma2(GW2(j), m, am[k]);
                        aq[k] = fma2(GW2(j), q, aq[k]);
                    }
                }
            }
            int hb = y * P_H + x0;
            #pragma unroll
            for (int k = 0; k < 4; k++) {
                ulonglong2 hp; hp.x = am[k]; hp.y = aq[k];
                s_h[hb + k] = hp;
            }
        }
    }
    __syncthreads();

    // ---- Phase 3: vertical 11-tap, strip-6; 9 warps x 6 = 54 rows exact ----
    float local = 0.0f;
    {
        int x  = tid & 31;
        int y0 = (tid >> 5) * 6;                 // 0..48; max read y = 63
        int ox  = blockIdx.x * TILE_W + x;
        int oyb = oyb0 + y0;
        if (ox < OUT_DIM && oyb < OUT_DIM) {
            u64 am[6], aq[6];
            #pragma unroll
            for (int k = 0; k < 6; k++) { am[k] = 0; aq[k] = 0; }
            const ulonglong2* bh = &s_h[y0 * P_H + x];
            #pragma unroll
            for (int j = 0; j < 16; j++) {
                ulonglong2 hp = bh[j * P_H];
                #pragma unroll
                for (int k = 0; k < 6; k++) {
                    int t = j - k;
                    if (t >= 0 && t < 11) {
                        am[k] = fma2(GW2(t), hp.x, am[k]);
                        aq[k] = fma2(GW2(t), hp.y, aq[k]);
                    }
                }
            }
            const float C1 = 1.0e-4f;    // (0.01)^2  — 255 scale folded out
            const float C2 = 9.0e-4f;    // (0.03)^2
            #pragma unroll
            for (int k = 0; k < 6; k++) {
                if ((oyb + k) < OUT_DIM) {
                    float a, b, srrdd, srd;
                    unpack2(am[k], a, b);
                    unpack2(aq[k], srrdd, srd);
                    float ab  = a * b;
                    float cov = srd - ab;
                    float var = srrdd - a * a - b * b;
                    float num = (2.0f * ab + C1) * (2.0f * cov + C2);
                    float den = (a * a + b * b + C1) * (var + C2);
                    local += __fdividef(num, den);
                }
            }
        }
    }

    #pragma unroll
    for (int o = 16; o > 0; o >>= 1)
        local += __shfl_down_sync(0xffffffff, local, o);
    if ((tid & 31) == 0) s_red[tid >> 5] = local;
    __syncthreads();
    if (tid < 16) {
        local = (tid < 9) ? s_red[tid] : 0.0f;
        #pragma unroll
        for (int o = 8; o > 0; o >>= 1)
            local += __shfl_down_sync(0xffff, local, o);
        if (tid == 0)
            atomicAdd(&out[z / 3], local * (1.0f / 732108.0f)); // 1/(3*494^2)
    }
}

extern "C" void kernel_launch(void* const* d_in, const int* in_sizes, int n_in,
                              void* d_out, int out_size) {
    const float* raw = (const float*)d_in[0];
    const float* dst = (const float*)d_in[1];
    float* out = (float*)d_out;

    cudaFuncSetAttribute(ssim_main, cudaFuncAttributeMaxDynamicSharedMemorySize,
                         SMEM_BYTES);

    ssim_zero<<<1, 32>>>(out);
    dim3 grid(16, 10, 96);   // 32x54 tiles over 494x494, z = b*3+c
    ssim_main<<<grid, NTHR, SMEM_BYTES>>>(raw, dst, out);
}